// round 5
// baseline (speedup 1.0000x reference)
#include <cuda_runtime.h>

#define RANK     64
#define WIN      11
#define TILE     512
#define THREADS  256
#define PADR     (TILE + 10)           // 522 padded rows (5 halo each side)
#define XSTRIDE  539                   // >= PADR + (PADR>>5) = 538 ; 539 mod 32 = 27, coprime

// dynamic smem (floats):
//   Wsh [64*64] = 4096, bsh [64], xsT [64][XSTRIDE] = 34496, pS [TILE][12] = 6144
#define SMEM_FLOATS (4096 + 64 + 64*XSTRIDE + TILE*12)
#define SMEM_BYTES  (SMEM_FLOATS * 4)   // 179200 B

__device__ __forceinline__ int gpos(int r) { return r + (r >> 5); }

__global__ __launch_bounds__(THREADS, 1)
void attn_w_kernel(const float* __restrict__ tf,
                   const float* __restrict__ W,
                   const float* __restrict__ b,
                   float* __restrict__ out,
                   int length)
{
    extern __shared__ float sm[];
    float* Wsh = sm;                       // [c][k] row-major
    float* bsh = Wsh + RANK * RANK;
    float* xsT = bsh + RANK;               // transposed tile [c][pos(row)]
    float* pS  = xsT + RANK * XSTRIDE;     // [row][12] row-major softmax weights

    const int tid  = threadIdx.x;
    const int row0 = blockIdx.x * TILE;

    // ---- W, b to shared ----
    #pragma unroll 4
    for (int i = tid; i < RANK * RANK; i += THREADS) Wsh[i] = W[i];
    if (tid < RANK) bsh[tid] = b[tid];

    // ---- load x tile transposed, gap-interleaved rows ----
    for (int e = tid; e < PADR * RANK; e += THREADS) {
        int rr = e >> 6;
        int c  = e & 63;
        int g  = row0 - 5 + rr;
        float v = (g >= 0 && g < length) ? tf[g * RANK + c] : 0.0f;
        xsT[c * XSTRIDE + gpos(rr)] = v;
    }
    __syncthreads();

    // ================= phase 1: fused GEMV(tanh) + banded scores, 2 rows/thread ==========
    const int r0 = 2 * tid;                // local rows r0, r0+1

    int po[12];                            // window positions for row pair (union, 12 slots)
    #pragma unroll
    for (int w = 0; w < 12; w++) po[w] = gpos(r0 + w);
    const int pp0 = gpos(r0 + 5);          // own-row positions
    const int pp1 = gpos(r0 + 6);

    float x0[RANK], x1[RANK];
    #pragma unroll
    for (int k = 0; k < RANK; k++) {
        x0[k] = xsT[k * XSTRIDE + pp0];
        x1[k] = xsT[k * XSTRIDE + pp1];
    }

    float s0[WIN], s1[WIN];
    #pragma unroll
    for (int w = 0; w < WIN; w++) { s0[w] = 0.0f; s1[w] = 0.0f; }

    #pragma unroll 1
    for (int c0 = 0; c0 < RANK; c0 += 4) {
        float v0[4], v1[4];
        #pragma unroll
        for (int cc = 0; cc < 4; cc++) {
            const int c = c0 + cc;
            float a0 = bsh[c];
            float a1 = a0;
            const float4* wr = (const float4*)(Wsh + c * RANK);
            #pragma unroll
            for (int k4 = 0; k4 < RANK / 4; k4++) {
                float4 wv = wr[k4];               // LDS.128 broadcast, serves both rows
                a0 = fmaf(x0[4*k4+0], wv.x, a0);  a1 = fmaf(x1[4*k4+0], wv.x, a1);
                a0 = fmaf(x0[4*k4+1], wv.y, a0);  a1 = fmaf(x1[4*k4+1], wv.y, a1);
                a0 = fmaf(x0[4*k4+2], wv.z, a0);  a1 = fmaf(x1[4*k4+2], wv.z, a1);
                a0 = fmaf(x0[4*k4+3], wv.w, a0);  a1 = fmaf(x1[4*k4+3], wv.w, a1);
            }
            float e0 = __expf(2.0f * a0); v0[cc] = 1.0f - __fdividef(2.0f, e0 + 1.0f);
            float e1 = __expf(2.0f * a1); v1[cc] = 1.0f - __fdividef(2.0f, e1 + 1.0f);
        }
        #pragma unroll
        for (int cc = 0; cc < 4; cc++) {
            const float* xc = xsT + (c0 + cc) * XSTRIDE;
            float lv[12];
            #pragma unroll
            for (int w = 0; w < 12; w++) lv[w] = xc[po[w]];   // 12 loads serve 2 rows
            #pragma unroll
            for (int w = 0; w < WIN; w++) {
                s0[w] = fmaf(lv[w],     v0[cc], s0[w]);
                s1[w] = fmaf(lv[w + 1], v1[cc], s1[w]);
            }
        }
    }

    // ---- scale + softmax, both rows ----
    float m0 = -1e30f, m1 = -1e30f;
    #pragma unroll
    for (int w = 0; w < WIN; w++) {
        s0[w] *= 0.125f; s1[w] *= 0.125f;
        m0 = fmaxf(m0, s0[w]); m1 = fmaxf(m1, s1[w]);
    }
    float t0 = 0.0f, t1 = 0.0f;
    #pragma unroll
    for (int w = 0; w < WIN; w++) {
        s0[w] = __expf(s0[w] - m0); t0 += s0[w];
        s1[w] = __expf(s1[w] - m1); t1 += s1[w];
    }
    float i0 = __fdividef(1.0f, t0);
    float i1 = __fdividef(1.0f, t1);
    #pragma unroll
    for (int w = 0; w < WIN; w++) { s0[w] *= i0; s1[w] *= i1; }

    // pack weights: pS[row][0..11], 3x STS.128 per row
    {
        float4* q0 = (float4*)(pS + r0 * 12);
        float4* q1 = (float4*)(pS + (r0 + 1) * 12);
        q0[0] = make_float4(s0[0], s0[1], s0[2],  s0[3]);
        q0[1] = make_float4(s0[4], s0[5], s0[6],  s0[7]);
        q0[2] = make_float4(s0[8], s0[9], s0[10], 0.0f);
        q1[0] = make_float4(s1[0], s1[1], s1[2],  s1[3]);
        q1[1] = make_float4(s1[4], s1[5], s1[6],  s1[7]);
        q1[2] = make_float4(s1[8], s1[9], s1[10], 0.0f);
    }
    __syncthreads();

    // ================= phase 2: output, c-major for coalesced STG, 2 rows/iter ==========
    const int c  = tid & 63;
    const int jb = (tid >> 6) * 2;
    const float* xc = xsT + c * XSTRIDE;

    #pragma unroll 1
    for (int jj = jb; jj < TILE; jj += 8) {
        // softmax weights via broadcast LDS.128 (3 per row)
        const float4* q0 = (const float4*)(pS + jj * 12);
        const float4* q1 = (const float4*)(pS + (jj + 1) * 12);
        float4 pa = q0[0], pb = q0[1], pc = q0[2];
        float4 pd = q1[0], pe = q1[1], pf = q1[2];
        float p0[WIN] = {pa.x, pa.y, pa.z, pa.w, pb.x, pb.y, pb.z, pb.w, pc.x, pc.y, pc.z};
        float p1[WIN] = {pd.x, pd.y, pd.z, pd.w, pe.x, pe.y, pe.z, pe.w, pf.x, pf.y, pf.z};

        float lv[12];
        #pragma unroll
        for (int w = 0; w < 12; w++) lv[w] = xc[gpos(jj + w)];  // 12 loads serve 2 rows

        float o0 = 0.0f, o1 = 0.0f;
        #pragma unroll
        for (int w = 0; w < WIN; w++) {
            o0 = fmaf(p0[w], lv[w],     o0);
            o1 = fmaf(p1[w], lv[w + 1], o1);
        }
        int gr = row0 + jj;
        if (gr     < length) out[gr * RANK + c]       = o0;   // coalesced
        if (gr + 1 < length) out[(gr + 1) * RANK + c] = o1;
    }
}

extern "C" void kernel_launch(void* const* d_in, const int* in_sizes, int n_in,
                              void* d_out, int out_size)
{
    const float* tf = (const float*)d_in[0];
    const float* W  = (const float*)d_in[1];
    const float* b  = (const float*)d_in[2];
    float* out      = (float*)d_out;

    const int length = in_sizes[0] / RANK;
    const int grid   = (length + TILE - 1) / TILE;

    cudaFuncSetAttribute(attn_w_kernel,
                         cudaFuncAttributeMaxDynamicSharedMemorySize, SMEM_BYTES);
    attn_w_kernel<<<grid, THREADS, SMEM_BYTES>>>(tf, W, b, out, length);
}

// round 8
// speedup vs baseline: 1.3657x; 1.3657x over previous
#include <cuda_runtime.h>

#define RANK     64
#define WIN      11
#define TILE     256
#define THREADS  256
#define PADR     266           // TILE + 2*5 halo
#define XSTRIDE  276           // 4*69; 69 mod 8 = 5 -> quad-banks distinct; 16B-aligned columns

// smem floats: Wsh 4096 + bsh 64 + xsT 64*276 = 17664 + pS 256*16 = 4096  -> 103680 B
#define SMEM_FLOATS (4096 + 64 + 64*XSTRIDE + TILE*16)
#define SMEM_BYTES  (SMEM_FLOATS * 4)

__device__ __forceinline__ unsigned long long pack2(float lo, float hi) {
    unsigned long long r;
    asm("mov.b64 %0, {%1,%2};" : "=l"(r) : "f"(lo), "f"(hi));
    return r;
}
__device__ __forceinline__ void unpack2(unsigned long long v, float& lo, float& hi) {
    asm("mov.b64 {%0,%1}, %2;" : "=f"(lo), "=f"(hi) : "l"(v));
}
__device__ __forceinline__ void ffma2(unsigned long long& d,
                                      unsigned long long a, unsigned long long b) {
    asm("fma.rn.f32x2 %0, %1, %2, %0;" : "+l"(d) : "l"(a), "l"(b));
}

__global__ __launch_bounds__(THREADS, 2)
void attn_w_kernel(const float* __restrict__ tf,
                   const float* __restrict__ W,
                   const float* __restrict__ b,
                   float* __restrict__ out,
                   int length)
{
    extern __shared__ float sm[];
    float* Wsh = sm;                       // [c][k] row-major
    float* bsh = Wsh + RANK * RANK;
    float* xsT = bsh + RANK;               // column-major tile [c][padded_row]
    float* pS  = xsT + RANK * XSTRIDE;     // [row][16] softmax weights (12 used)

    const int tid  = threadIdx.x;
    const int row0 = blockIdx.x * TILE;

    // ---- W, b to shared (coalesced) ----
    #pragma unroll 4
    for (int i = tid; i < RANK * RANK; i += THREADS) Wsh[i] = W[i];
    if (tid < RANK) bsh[tid] = b[tid];

    // ---- load x tile transposed ----
    for (int e = tid; e < PADR * RANK; e += THREADS) {
        int rr = e >> 6;
        int c  = e & 63;
        int g  = row0 - 5 + rr;
        float v = (g >= 0 && g < length) ? tf[g * RANK + c] : 0.0f;
        xsT[c * XSTRIDE + rr] = v;
    }
    __syncthreads();

    // ================= phase 1: row j = tid ==================================
    const int j = tid;
    const int p = j + 5;                   // own padded row

    // preload own x row as packed f32x2 pairs (k even/odd)
    unsigned long long x2[RANK / 2];
    #pragma unroll
    for (int k2 = 0; k2 < RANK / 2; k2++)
        x2[k2] = pack2(xsT[(2 * k2) * XSTRIDE + p],
                       xsT[(2 * k2 + 1) * XSTRIDE + p]);

    float s[WIN];
    #pragma unroll
    for (int w = 0; w < WIN; w++) s[w] = 0.0f;

    // fused GEMV(tanh, f32x2) + banded score accumulation
    #pragma unroll 1
    for (int cq = 0; cq < 16; cq++) {
        float v[4];
        #pragma unroll
        for (int cc = 0; cc < 4; cc++) {
            const int c = cq * 4 + cc;
            unsigned long long acc2 = pack2(bsh[c], 0.0f);
            const double2* wr = (const double2*)(Wsh + c * RANK);
            #pragma unroll
            for (int k8 = 0; k8 < 8; k8++) {
                double2 wa = wr[2 * k8];          // LDS.128 broadcast
                double2 wb = wr[2 * k8 + 1];
                ffma2(acc2, x2[4 * k8 + 0], __double_as_longlong(wa.x));
                ffma2(acc2, x2[4 * k8 + 1], __double_as_longlong(wa.y));
                ffma2(acc2, x2[4 * k8 + 2], __double_as_longlong(wb.x));
                ffma2(acc2, x2[4 * k8 + 3], __double_as_longlong(wb.y));
            }
            float lo, hi; unpack2(acc2, lo, hi);
            float a = lo + hi;
            float e = __expf(2.0f * a);
            v[cc] = 1.0f - __fdividef(2.0f, e + 1.0f);   // tanh
        }
        #pragma unroll
        for (int cc = 0; cc < 4; cc++) {
            const float* xc = xsT + (cq * 4 + cc) * XSTRIDE + j;  // rows j..j+10
            #pragma unroll
            for (int w = 0; w < WIN; w++)
                s[w] = fmaf(xc[w], v[cc], s[w]);   // lanes consecutive j: conflict-free
        }
    }

    // ---- scale + softmax over window ----
    float mx = -1e30f;
    #pragma unroll
    for (int w = 0; w < WIN; w++) { s[w] *= 0.125f; mx = fmaxf(mx, s[w]); }
    float ssum = 0.0f;
    #pragma unroll
    for (int w = 0; w < WIN; w++) { s[w] = __expf(s[w] - mx); ssum += s[w]; }
    float inv = __fdividef(1.0f, ssum);

    {
        float4* q = (float4*)(pS + j * 16);
        q[0] = make_float4(s[0] * inv, s[1] * inv, s[2]  * inv, s[3] * inv);
        q[1] = make_float4(s[4] * inv, s[5] * inv, s[6]  * inv, s[7] * inv);
        q[2] = make_float4(s[8] * inv, s[9] * inv, s[10] * inv, 0.0f);
    }
    __syncthreads();

    // ================= phase 2: output, vectorized window loads ==============
    // lane = column (c and c+32); warp handles 4-row blocks
    const int lane = tid & 31;
    const int wrp  = tid >> 5;

    #pragma unroll 1
    for (int it = 0; it < TILE / 32; it++) {
        const int jj = 4 * wrp + 32 * it;      // 4-aligned row block

        // softmax weights for 4 rows (broadcast LDS.128, reused for both columns)
        float pw[4][12];
        #pragma unroll
        for (int r = 0; r < 4; r++) {
            const float4* pr = (const float4*)(pS + (jj + r) * 16);
            float4 a = pr[0], bq = pr[1], cq = pr[2];
            pw[r][0] = a.x;  pw[r][1] = a.y;  pw[r][2]  = a.z;  pw[r][3] = a.w;
            pw[r][4] = bq.x; pw[r][5] = bq.y; pw[r][6]  = bq.z; pw[r][7] = bq.w;
            pw[r][8] = cq.x; pw[r][9] = cq.y; pw[r][10] = cq.z; pw[r][11] = 0.0f;
        }

        #pragma unroll
        for (int half = 0; half < 2; half++) {
            const int c = lane + 32 * half;
            // 16 padded rows jj..jj+15 of column c: 4 aligned LDS.128 at wavefront floor
            const float4* xq = (const float4*)(xsT + c * XSTRIDE + jj);
            float4 q0 = xq[0], q1 = xq[1], q2 = xq[2], q3 = xq[3];
            float fx[16] = {q0.x, q0.y, q0.z, q0.w,  q1.x, q1.y, q1.z, q1.w,
                            q2.x, q2.y, q2.z, q2.w,  q3.x, q3.y, q3.z, q3.w};
            #pragma unroll
            for (int r = 0; r < 4; r++) {
                float o = 0.0f;
                #pragma unroll
                for (int w = 0; w < WIN; w++)
                    o = fmaf(pw[r][w], fx[r + w], o);
                int gr = row0 + jj + r;
                if (gr < length) out[gr * RANK + c] = o;   // coalesced
            }
        }
    }
}

extern "C" void kernel_launch(void* const* d_in, const int* in_sizes, int n_in,
                              void* d_out, int out_size)
{
    const float* tf = (const float*)d_in[0];
    const float* W  = (const float*)d_in[1];
    const float* b  = (const float*)d_in[2];
    float* out      = (float*)d_out;

    const int length = in_sizes[0] / RANK;
    const int grid   = (length + TILE - 1) / TILE;

    cudaFuncSetAttribute(attn_w_kernel,
                         cudaFuncAttributeMaxDynamicSharedMemorySize, SMEM_BYTES);
    attn_w_kernel<<<grid, THREADS, SMEM_BYTES>>>(tf, W, b, out, length);
}

// round 13
// speedup vs baseline: 1.6121x; 1.1804x over previous
#include <cuda_runtime.h>

#define RANK    64
#define WIN     11
#define TILE    256
#define THREADS 256
#define PADR    266           // TILE + 2*5 halo
#define XS      276           // lane-bank-verified stride
#define PSS     12            // pS row stride

#define PS_OFF  (RANK * XS)                 // 17664
#define BS_OFF  (PS_OFF + TILE * PSS)       // +3072
#define SMEM_FLOATS (BS_OFF + RANK)
#define SMEM_BYTES  (SMEM_FLOATS * 4)       // 83200 B -> 2 CTAs/SM

// W in GEMV B-fragment layout, bf16 hi/lo split: index (kc*8+nt)*32+lane -> (b0,b1)
__device__ uint2 g_WHI[2048];
__device__ uint2 g_WLO[2048];

// pack (even,odd) floats -> bf16x2 with even in LOWER 16 bits
static __device__ __forceinline__ unsigned pk2(float even, float odd) {
    unsigned d;
    asm("cvt.rn.bf16x2.f32 %0, %1, %2;" : "=r"(d) : "f"(odd), "f"(even));
    return d;
}
static __device__ __forceinline__ void split2(float a, float b, unsigned& h, unsigned& l) {
    h = pk2(a, b);
    float ha = __uint_as_float(h << 16);
    float hb = __uint_as_float(h & 0xffff0000u);
    l = pk2(a - ha, b - hb);
}
static __device__ __forceinline__ void mma16(float* d, const unsigned* a,
                                             unsigned b0, unsigned b1) {
    asm volatile(
        "mma.sync.aligned.m16n8k16.row.col.f32.bf16.bf16.f32 "
        "{%0,%1,%2,%3}, {%4,%5,%6,%7}, {%8,%9}, {%0,%1,%2,%3};"
        : "+f"(d[0]), "+f"(d[1]), "+f"(d[2]), "+f"(d[3])
        : "r"(a[0]), "r"(a[1]), "r"(a[2]), "r"(a[3]), "r"(b0), "r"(b1));
}

__global__ void prep_kernel(const float* __restrict__ W) {
    int e = blockIdx.x * 128 + threadIdx.x;     // 0..2047
    int lane = e & 31, set = e >> 5;
    int kc = set >> 3, nt = set & 7;
    int q = lane >> 2, t = lane & 3;
    int n = nt * 8 + q;
    int k0 = kc * 16 + 2 * t;
    float v0 = W[n * RANK + k0],     v1 = W[n * RANK + k0 + 1];
    float v2 = W[n * RANK + k0 + 8], v3 = W[n * RANK + k0 + 9];
    unsigned h01, l01, h23, l23;
    split2(v0, v1, h01, l01);
    split2(v2, v3, h23, l23);
    g_WHI[e] = make_uint2(h01, h23);
    g_WLO[e] = make_uint2(l01, l23);
}

__global__ __launch_bounds__(THREADS, 2)
void attn_w_kernel(const float* __restrict__ tf,
                   const float* __restrict__ b,
                   float* __restrict__ out,
                   int length)
{
    extern __shared__ float sm[];
    float* xsT = sm;            // [c][padded_row] stride XS
    float* pS  = sm + PS_OFF;   // [row][PSS]
    float* bsh = sm + BS_OFF;

    const int tid  = threadIdx.x;
    const int wid  = tid >> 5;
    const int lane = tid & 31;
    const int q    = lane >> 2;
    const int t    = lane & 3;
    const int row0 = blockIdx.x * TILE;
    const int rbase = wid * 32;

    for (int e = tid; e < PADR * RANK; e += THREADS) {
        int rr = e >> 6, c = e & 63;
        int g = row0 - 5 + rr;
        xsT[c * XS + rr] = (g >= 0 && g < length) ? tf[g * RANK + c] : 0.0f;
    }
    if (tid < RANK) bsh[tid] = b[tid];
    __syncthreads();

    // ============ phase 1: per-warp 32 rows = two m16 tiles ============
    #pragma unroll 1
    for (int mi = 0; mi < 2; mi++) {
        // ---- GEMV via MMA: dv[nt][4], 3-pass bf16 split ----
        float dv[8][4];
        #pragma unroll
        for (int i = 0; i < 8; i++)
            { dv[i][0] = 0.f; dv[i][1] = 0.f; dv[i][2] = 0.f; dv[i][3] = 0.f; }

        const int P = rbase + 16 * mi + 5 + q;      // padded row of A-row q
        #pragma unroll
        for (int kc = 0; kc < 4; kc++) {
            const int c0 = 16 * kc + 2 * t;
            float x0 = xsT[c0 * XS + P],           x1 = xsT[(c0 + 1) * XS + P];
            float x2 = xsT[c0 * XS + P + 8],       x3 = xsT[(c0 + 1) * XS + P + 8];
            float x4 = xsT[(c0 + 8) * XS + P],     x5 = xsT[(c0 + 9) * XS + P];
            float x6 = xsT[(c0 + 8) * XS + P + 8], x7 = xsT[(c0 + 9) * XS + P + 8];
            unsigned ah[4], al[4];
            split2(x0, x1, ah[0], al[0]);
            split2(x2, x3, ah[1], al[1]);
            split2(x4, x5, ah[2], al[2]);
            split2(x6, x7, ah[3], al[3]);
            #pragma unroll
            for (int nt = 0; nt < 8; nt++) {
                uint2 wh = g_WHI[(kc * 8 + nt) * 32 + lane];
                uint2 wl = g_WLO[(kc * 8 + nt) * 32 + lane];
                mma16(dv[nt], ah, wh.x, wh.y);
                mma16(dv[nt], al, wh.x, wh.y);
                mma16(dv[nt], ah, wl.x, wl.y);
            }
        }

        // ---- bias + tanh + fold 1/8; re-split as score A-frags ----
        unsigned vh[8][2], vl[8][2];
        #pragma unroll
        for (int nt = 0; nt < 8; nt++) {
            float2 bb = *(const float2*)(bsh + nt * 8 + 2 * t);
            #pragma unroll
            for (int r = 0; r < 4; r++) {
                float a = dv[nt][r] + ((r & 1) ? bb.y : bb.x);
                float e = __expf(2.0f * a);
                dv[nt][r] = (1.0f - __fdividef(2.0f, e + 1.0f)) * 0.125f;
            }
            split2(dv[nt][0], dv[nt][1], vh[nt][0], vl[nt][0]);  // row q
            split2(dv[nt][2], dv[nt][3], vh[nt][1], vl[nt][1]);  // row q+8
        }

        // ---- score MMA over 4 n-tiles of padded columns ----
        #pragma unroll
        for (int nj = 0; nj < 4; nj++) {
            const int p = rbase + 16 * mi + 8 * nj + q;
            float ds[4] = {0.f, 0.f, 0.f, 0.f};
            #pragma unroll
            for (int kc = 0; kc < 4; kc++) {
                const int c0 = 16 * kc + 2 * t;
                float y0 = xsT[c0 * XS + p],       y1 = xsT[(c0 + 1) * XS + p];
                float y2 = xsT[(c0 + 8) * XS + p], y3 = xsT[(c0 + 9) * XS + p];
                unsigned bh0, bl0, bh1, bl1;
                split2(y0, y1, bh0, bl0);
                split2(y2, y3, bh1, bl1);
                unsigned ah[4] = {vh[2 * kc][0], vh[2 * kc][1],
                                  vh[2 * kc + 1][0], vh[2 * kc + 1][1]};
                unsigned al[4] = {vl[2 * kc][0], vl[2 * kc][1],
                                  vl[2 * kc + 1][0], vl[2 * kc + 1][1]};
                mma16(ds, ah, bh0, bh1);
                mma16(ds, al, bh0, bh1);
                mma16(ds, ah, bl0, bl1);
            }
            // band extraction: w = p_col - row
            #pragma unroll
            for (int r = 0; r < 4; r++) {
                int dr = r >> 1, dk = r & 1;
                int w = 8 * nj + 2 * t + dk - q - 8 * dr;
                if (w >= 0 && w < WIN)
                    pS[(rbase + 16 * mi + q + 8 * dr) * PSS + w] = ds[r];
            }
        }
    }
    __syncwarp();

    // ---- softmax over window, thread row = tid ----
    {
        const float4* pr = (const float4*)(pS + tid * PSS);
        float4 A = pr[0], B = pr[1], C = pr[2];
        float s[WIN] = {A.x, A.y, A.z, A.w, B.x, B.y, B.z, B.w, C.x, C.y, C.z};
        float mx = -1e30f;
        #pragma unroll
        for (int w = 0; w < WIN; w++) mx = fmaxf(mx, s[w]);
        float ssum = 0.0f;
        #pragma unroll
        for (int w = 0; w < WIN; w++) { s[w] = __expf(s[w] - mx); ssum += s[w]; }
        float inv = __fdividef(1.0f, ssum);
        float4* pw = (float4*)(pS + tid * PSS);
        pw[0] = make_float4(s[0] * inv, s[1] * inv, s[2]  * inv, s[3] * inv);
        pw[1] = make_float4(s[4] * inv, s[5] * inv, s[6]  * inv, s[7] * inv);
        pw[2] = make_float4(s[8] * inv, s[9] * inv, s[10] * inv, 0.0f);
    }
    __syncthreads();

    // ============ phase 2: output, c-major coalesced ============
    #pragma unroll 1
    for (int it = 0; it < TILE / 32; it++) {
        const int jj = 4 * wid + 32 * it;
        #pragma unroll
        for (int half = 0; half < 2; half++) {
            const int c = lane + 32 * half;
            const float4* xq = (const float4*)(xsT + c * XS + jj);
            float4 q0 = xq[0], q1 = xq[1], q2 = xq[2], q3 = xq[3];
            float fx[16] = {q0.x, q0.y, q0.z, q0.w,  q1.x, q1.y, q1.z, q1.w,
                            q2.x, q2.y, q2.z, q2.w,  q3.x, q3.y, q3.z, q3.w};
            #pragma unroll
            for (int r = 0; r < 4; r++) {
                const float4* pr = (const float4*)(pS + (jj + r) * PSS);
                float4 pa = pr[0], pb = pr[1], pc = pr[2];
                float pw[WIN] = {pa.x, pa.y, pa.z, pa.w, pb.x, pb.y, pb.z, pb.w,
                                 pc.x, pc.y, pc.z};
                float o = 0.0f;
                #pragma unroll
                for (int w = 0; w < WIN; w++) o = fmaf(pw[w], fx[r + w], o);
                int gr = row0 + jj + r;
                if (gr < length) out[gr * RANK + c] = o;
            }
        }
    }
}

extern "C" void kernel_launch(void* const* d_in, const int* in_sizes, int n_in,
                              void* d_out, int out_size)
{
    const float* tf = (const float*)d_in[0];
    const float* W  = (const float*)d_in[1];
    const float* b  = (const float*)d_in[2];
    float* out      = (float*)d_out;

    const int length = in_sizes[0] / RANK;
    const int grid   = (length + TILE - 1) / TILE;

    prep_kernel<<<16, 128>>>(W);
    cudaFuncSetAttribute(attn_w_kernel,
                         cudaFuncAttributeMaxDynamicSharedMemorySize, SMEM_BYTES);
    attn_w_kernel<<<grid, THREADS, SMEM_BYTES>>>(tf, b, out, length);
}

// round 14
// speedup vs baseline: 1.7306x; 1.0735x over previous
#include <cuda_runtime.h>

#define RANK    64
#define WIN     11
#define TILE    256
#define THREADS 256
#define PADR    266           // TILE + 2*5 halo
#define XS      276           // lane-bank-verified stride
#define PSS     12            // pS row stride

#define PS_OFF  (RANK * XS)                 // 17664
#define BS_OFF  (PS_OFF + TILE * PSS)       // +3072
#define SMEM_FLOATS (BS_OFF + RANK)
#define SMEM_BYTES  (SMEM_FLOATS * 4)       // 83200 B -> 2 CTAs/SM

// tanh scale: 0.125 (1/sqrt(64)·softmax fold) * log2(e) -> scores in log2 domain
#define VSCALE 0.18033688011112042f

// W in GEMV B-fragment layout, bf16 hi/lo split: index (kc*8+nt)*32+lane -> (b0,b1)
__device__ uint2 g_WHI[2048];
__device__ uint2 g_WLO[2048];

// pack (even,odd) floats -> bf16x2 with even in LOWER 16 bits
static __device__ __forceinline__ unsigned pk2(float even, float odd) {
    unsigned d;
    asm("cvt.rn.bf16x2.f32 %0, %1, %2;" : "=r"(d) : "f"(odd), "f"(even));
    return d;
}
static __device__ __forceinline__ void split2(float a, float b, unsigned& h, unsigned& l) {
    h = pk2(a, b);
    float ha = __uint_as_float(h << 16);
    float hb = __uint_as_float(h & 0xffff0000u);
    l = pk2(a - ha, b - hb);
}
static __device__ __forceinline__ float tanhapx(float x) {
    float r; asm("tanh.approx.f32 %0, %1;" : "=f"(r) : "f"(x)); return r;
}
static __device__ __forceinline__ float ex2apx(float x) {
    float r; asm("ex2.approx.f32 %0, %1;" : "=f"(r) : "f"(x)); return r;
}
static __device__ __forceinline__ void mma16(float* d, const unsigned* a,
                                             unsigned b0, unsigned b1) {
    asm volatile(
        "mma.sync.aligned.m16n8k16.row.col.f32.bf16.bf16.f32 "
        "{%0,%1,%2,%3}, {%4,%5,%6,%7}, {%8,%9}, {%0,%1,%2,%3};"
        : "+f"(d[0]), "+f"(d[1]), "+f"(d[2]), "+f"(d[3])
        : "r"(a[0]), "r"(a[1]), "r"(a[2]), "r"(a[3]), "r"(b0), "r"(b1));
}

__global__ void prep_kernel(const float* __restrict__ W) {
    int e = blockIdx.x * 128 + threadIdx.x;     // 0..2047
    int lane = e & 31, set = e >> 5;
    int kc = set >> 3, nt = set & 7;
    int q = lane >> 2, t = lane & 3;
    int n = nt * 8 + q;
    int k0 = kc * 16 + 2 * t;
    float v0 = W[n * RANK + k0],     v1 = W[n * RANK + k0 + 1];
    float v2 = W[n * RANK + k0 + 8], v3 = W[n * RANK + k0 + 9];
    unsigned h01, l01, h23, l23;
    split2(v0, v1, h01, l01);
    split2(v2, v3, h23, l23);
    g_WHI[e] = make_uint2(h01, h23);
    g_WLO[e] = make_uint2(l01, l23);
}

__global__ __launch_bounds__(THREADS, 2)
void attn_w_kernel(const float* __restrict__ tf,
                   const float* __restrict__ b,
                   float* __restrict__ out,
                   int length)
{
    extern __shared__ float sm[];
    float* xsT = sm;            // [c][padded_row] stride XS
    float* pS  = sm + PS_OFF;   // [row][PSS]
    float* bsh = sm + BS_OFF;

    const int tid  = threadIdx.x;
    const int wid  = tid >> 5;
    const int lane = tid & 31;
    const int q    = lane >> 2;
    const int t    = lane & 3;
    const int row0 = blockIdx.x * TILE;
    const int rbase = wid * 32;

    for (int e = tid; e < PADR * RANK; e += THREADS) {
        int rr = e >> 6, c = e & 63;
        int g = row0 - 5 + rr;
        xsT[c * XS + rr] = (g >= 0 && g < length) ? tf[g * RANK + c] : 0.0f;
    }
    if (tid < RANK) bsh[tid] = b[tid];
    __syncthreads();

    // ============ phase 1: per-warp 32 rows = two m16 tiles ============
    #pragma unroll 1
    for (int mi = 0; mi < 2; mi++) {
        // ---- GEMV via MMA: dv[nt][4] initialized with bias, 3-pass bf16 split ----
        float dv[8][4];
        #pragma unroll
        for (int nt = 0; nt < 8; nt++) {
            float2 bb = *(const float2*)(bsh + nt * 8 + 2 * t);
            dv[nt][0] = bb.x; dv[nt][1] = bb.y;
            dv[nt][2] = bb.x; dv[nt][3] = bb.y;
        }

        const int P = rbase + 16 * mi + 5 + q;      // padded row of A-row q
        #pragma unroll
        for (int kc = 0; kc < 4; kc++) {
            const int c0 = 16 * kc + 2 * t;
            float x0 = xsT[c0 * XS + P],           x1 = xsT[(c0 + 1) * XS + P];
            float x2 = xsT[c0 * XS + P + 8],       x3 = xsT[(c0 + 1) * XS + P + 8];
            float x4 = xsT[(c0 + 8) * XS + P],     x5 = xsT[(c0 + 9) * XS + P];
            float x6 = xsT[(c0 + 8) * XS + P + 8], x7 = xsT[(c0 + 9) * XS + P + 8];
            unsigned ah[4], al[4];
            split2(x0, x1, ah[0], al[0]);
            split2(x2, x3, ah[1], al[1]);
            split2(x4, x5, ah[2], al[2]);
            split2(x6, x7, ah[3], al[3]);
            #pragma unroll
            for (int nt = 0; nt < 8; nt++) {
                uint2 wh = g_WHI[(kc * 8 + nt) * 32 + lane];
                uint2 wl = g_WLO[(kc * 8 + nt) * 32 + lane];
                mma16(dv[nt], ah, wh.x, wh.y);
                mma16(dv[nt], al, wh.x, wh.y);
                mma16(dv[nt], ah, wl.x, wl.y);
            }
        }

        // ---- tanh (1 MUFU) + fold 0.125*log2e; re-split as score A-frags ----
        unsigned vh[8][2], vl[8][2];
        #pragma unroll
        for (int nt = 0; nt < 8; nt++) {
            #pragma unroll
            for (int r = 0; r < 4; r++)
                dv[nt][r] = tanhapx(dv[nt][r]) * VSCALE;
            split2(dv[nt][0], dv[nt][1], vh[nt][0], vl[nt][0]);  // row q
            split2(dv[nt][2], dv[nt][3], vh[nt][1], vl[nt][1]);  // row q+8
        }

        // ---- score MMA over 4 n-tiles of padded columns ----
        #pragma unroll
        for (int nj = 0; nj < 4; nj++) {
            const int p = rbase + 16 * mi + 8 * nj + q;
            float ds[4] = {0.f, 0.f, 0.f, 0.f};
            #pragma unroll
            for (int kc = 0; kc < 4; kc++) {
                const int c0 = 16 * kc + 2 * t;
                float y0 = xsT[c0 * XS + p],       y1 = xsT[(c0 + 1) * XS + p];
                float y2 = xsT[(c0 + 8) * XS + p], y3 = xsT[(c0 + 9) * XS + p];
                unsigned bh0, bl0, bh1, bl1;
                split2(y0, y1, bh0, bl0);
                split2(y2, y3, bh1, bl1);
                unsigned ah[4] = {vh[2 * kc][0], vh[2 * kc][1],
                                  vh[2 * kc + 1][0], vh[2 * kc + 1][1]};
                unsigned al[4] = {vl[2 * kc][0], vl[2 * kc][1],
                                  vl[2 * kc + 1][0], vl[2 * kc + 1][1]};
                mma16(ds, ah, bh0, bh1);
                mma16(ds, al, bh0, bh1);
                mma16(ds, ah, bl0, bl1);
            }
            // band extraction: w = p_col - row
            #pragma unroll
            for (int r = 0; r < 4; r++) {
                int dr = r >> 1, dk = r & 1;
                int w = 8 * nj + 2 * t + dk - q - 8 * dr;
                if (w >= 0 && w < WIN)
                    pS[(rbase + 16 * mi + q + 8 * dr) * PSS + w] = ds[r];
            }
        }
    }
    __syncwarp();

    // ---- softmax over window (scores already in log2 domain), row = tid ----
    {
        const float4* pr = (const float4*)(pS + tid * PSS);
        float4 A = pr[0], B = pr[1], C = pr[2];
        float s[WIN] = {A.x, A.y, A.z, A.w, B.x, B.y, B.z, B.w, C.x, C.y, C.z};
        float mx = -1e30f;
        #pragma unroll
        for (int w = 0; w < WIN; w++) mx = fmaxf(mx, s[w]);
        float ssum = 0.0f;
        #pragma unroll
        for (int w = 0; w < WIN; w++) { s[w] = ex2apx(s[w] - mx); ssum += s[w]; }
        float inv = __fdividef(1.0f, ssum);
        float4* pw = (float4*)(pS + tid * PSS);
        pw[0] = make_float4(s[0] * inv, s[1] * inv, s[2]  * inv, s[3] * inv);
        pw[1] = make_float4(s[4] * inv, s[5] * inv, s[6]  * inv, s[7] * inv);
        pw[2] = make_float4(s[8] * inv, s[9] * inv, s[10] * inv, 0.0f);
    }
    __syncthreads();

    // ============ phase 2: output, c-major coalesced ============
    #pragma unroll 1
    for (int it = 0; it < TILE / 32; it++) {
        const int jj = 4 * wid + 32 * it;
        #pragma unroll
        for (int half = 0; half < 2; half++) {
            const int c = lane + 32 * half;
            const float4* xq = (const float4*)(xsT + c * XS + jj);
            float4 q0 = xq[0], q1 = xq[1], q2 = xq[2], q3 = xq[3];
            float fx[16] = {q0.x, q0.y, q0.z, q0.w,  q1.x, q1.y, q1.z, q1.w,
                            q2.x, q2.y, q2.z, q2.w,  q3.x, q3.y, q3.z, q3.w};
            #pragma unroll
            for (int r = 0; r < 4; r++) {
                const float4* pr = (const float4*)(pS + (jj + r) * PSS);
                float4 pa = pr[0], pb = pr[1], pc = pr[2];
                float pw[WIN] = {pa.x, pa.y, pa.z, pa.w, pb.x, pb.y, pb.z, pb.w,
                                 pc.x, pc.y, pc.z};
                float o = 0.0f;
                #pragma unroll
                for (int w = 0; w < WIN; w++) o = fmaf(pw[w], fx[r + w], o);
                int gr = row0 + jj + r;
                if (gr < length) out[gr * RANK + c] = o;
            }
        }
    }
}

extern "C" void kernel_launch(void* const* d_in, const int* in_sizes, int n_in,
                              void* d_out, int out_size)
{
    const float* tf = (const float*)d_in[0];
    const float* W  = (const float*)d_in[1];
    const float* b  = (const float*)d_in[2];
    float* out      = (float*)d_out;

    const int length = in_sizes[0] / RANK;
    const int grid   = (length + TILE - 1) / TILE;

    prep_kernel<<<16, 128>>>(W);
    cudaFuncSetAttribute(attn_w_kernel,
                         cudaFuncAttributeMaxDynamicSharedMemorySize, SMEM_BYTES);
    attn_w_kernel<<<grid, THREADS, SMEM_BYTES>>>(tf, b, out, length);
}